// round 1
// baseline (speedup 1.0000x reference)
#include <cuda_runtime.h>
#include <math.h>

#define B_  4
#define T_  2048
#define E_  1024
#define H_  16
#define DH_ 64
#define BT_ (B_*T_)
#define BTE_ (B_*T_*E_)

// -------- scratch (device globals; no allocation allowed) --------
__device__ float g_Wq[E_*E_];
__device__ float g_Wk[E_*E_];
__device__ float g_Wv[E_*E_];
__device__ float g_q[BTE_];
__device__ float g_k[BTE_];
__device__ float g_v[BTE_];
__device__ float g_qh[BTE_];
__device__ float g_attn[BTE_];
__device__ float g_ctx[BTE_];
__device__ float g_K1[B_*64*E_];
__device__ float g_V1[B_*64*E_];
__device__ float g_K2[B_*32*E_];
__device__ float g_V2[B_*32*E_];

// -------- fold LoRA: Weff = W + 2 * A @ Bm  (A: E x 8, Bm: 8 x E) --------
__global__ void fold_lora_kernel(const float* __restrict__ W,
                                 const float* __restrict__ A,
                                 const float* __restrict__ Bm,
                                 float* __restrict__ Weff) {
    int idx = blockIdx.x * blockDim.x + threadIdx.x;   // over E*E
    int n = idx >> 10;          // row (output feature)
    int k = idx & 1023;         // col (input feature)
    float acc = W[idx];
    #pragma unroll
    for (int r = 0; r < 8; ++r)
        acc += 2.0f * A[n * 8 + r] * Bm[r * E_ + k];
    Weff[idx] = acc;
}

// -------- SGEMM NT: C[m,n] = (acc? C : 0) + alpha * sum_k A[m,k]*B[n,k] ----
// A: M x K row-major, B: N x K row-major. 128x128x8 tile, 256 threads, 8x8 micro.
__global__ void __launch_bounds__(256)
sgemm_nt_kernel(const float* __restrict__ A, const float* __restrict__ Bmat,
                float* __restrict__ C, int M, int N, int K,
                const float* __restrict__ gate, int accumulate) {
    __shared__ float As[8][128];
    __shared__ float Bs[8][128];

    const int bm = blockIdx.y * 128;
    const int bn = blockIdx.x * 128;
    const int tid = threadIdx.x;
    const int lrow  = tid >> 1;          // 0..127
    const int lcol4 = (tid & 1) * 4;     // 0 or 4
    const int ty = tid >> 4;             // 0..15
    const int tx = tid & 15;             // 0..15
    const int trow = ty * 8;
    const int tcol = tx * 8;

    float acc[8][8];
    #pragma unroll
    for (int i = 0; i < 8; ++i)
        #pragma unroll
        for (int j = 0; j < 8; ++j) acc[i][j] = 0.0f;

    const float* aptr = A + (size_t)(bm + lrow) * K + lcol4;
    const float* bptr = Bmat + (size_t)(bn + lrow) * K + lcol4;

    for (int k0 = 0; k0 < K; k0 += 8) {
        float4 a4 = *(const float4*)(aptr + k0);
        float4 b4 = *(const float4*)(bptr + k0);
        As[lcol4 + 0][lrow] = a4.x; As[lcol4 + 1][lrow] = a4.y;
        As[lcol4 + 2][lrow] = a4.z; As[lcol4 + 3][lrow] = a4.w;
        Bs[lcol4 + 0][lrow] = b4.x; Bs[lcol4 + 1][lrow] = b4.y;
        Bs[lcol4 + 2][lrow] = b4.z; Bs[lcol4 + 3][lrow] = b4.w;
        __syncthreads();
        #pragma unroll
        for (int kk = 0; kk < 8; ++kk) {
            float a[8], b[8];
            *(float4*)&a[0] = *(const float4*)&As[kk][trow];
            *(float4*)&a[4] = *(const float4*)&As[kk][trow + 4];
            *(float4*)&b[0] = *(const float4*)&Bs[kk][tcol];
            *(float4*)&b[4] = *(const float4*)&Bs[kk][tcol + 4];
            #pragma unroll
            for (int i = 0; i < 8; ++i)
                #pragma unroll
                for (int j = 0; j < 8; ++j)
                    acc[i][j] = fmaf(a[i], b[j], acc[i][j]);
        }
        __syncthreads();
    }

    float alpha = 1.0f;
    if (gate) alpha = 1.0f / (1.0f + expf(-__ldg(gate)));   // sigmoid(gate)

    #pragma unroll
    for (int i = 0; i < 8; ++i) {
        float* crow = C + (size_t)(bm + trow + i) * N + bn + tcol;
        #pragma unroll
        for (int j = 0; j < 8; ++j) {
            float v = alpha * acc[i][j];
            if (accumulate) v += crow[j];
            crow[j] = v;
        }
    }
}

// -------- flash attention, causal + alibi(+slope*(i-j)), fp32 -------------
// grid: (T/64, B*H), 256 threads. Tiles 64(q) x 64(k) x 64(d).
__global__ void __launch_bounds__(256)
flash_attn_kernel(const float* __restrict__ Q, const float* __restrict__ K,
                  const float* __restrict__ V, const float* __restrict__ slopes,
                  float* __restrict__ O) {
    __shared__ float Qs[64][64];   // [d][m]
    __shared__ float Ks[64][64];   // [d][n]
    __shared__ float Vs[64][64];   // [n][d]
    __shared__ float Ps[64][65];   // [m][n] padded

    const int bh = blockIdx.y;
    const int b = bh / H_;
    const int h = bh % H_;
    const int q0 = blockIdx.x * 64;
    const int tid = threadIdx.x;
    const int tx = tid & 15;
    const int ty = tid >> 4;

    // load Q tile transposed: Qs[d][m]
    {
        int row = tid >> 2;
        int d0 = (tid & 3) * 16;
        const float* src = Q + ((size_t)(b * T_ + q0 + row) * E_) + h * 64 + d0;
        #pragma unroll
        for (int u = 0; u < 4; ++u) {
            float4 v4 = *(const float4*)(src + u * 4);
            Qs[d0 + u*4 + 0][row] = v4.x; Qs[d0 + u*4 + 1][row] = v4.y;
            Qs[d0 + u*4 + 2][row] = v4.z; Qs[d0 + u*4 + 3][row] = v4.w;
        }
    }
    const float slope = slopes[h];

    float o[4][4];
    float m_prev[4], l_prev[4];
    #pragma unroll
    for (int i = 0; i < 4; ++i) {
        m_prev[i] = -1e30f; l_prev[i] = 0.0f;
        #pragma unroll
        for (int j = 0; j < 4; ++j) o[i][j] = 0.0f;
    }

    const int ntiles = blockIdx.x + 1;   // causal
    for (int jt = 0; jt < ntiles; ++jt) {
        const int n0 = jt * 64;
        // load K (transposed) and V (natural)
        {
            int row = tid >> 2;
            int d0 = (tid & 3) * 16;
            const float* ksrc = K + ((size_t)(b * T_ + n0 + row) * E_) + h * 64 + d0;
            const float* vsrc = V + ((size_t)(b * T_ + n0 + row) * E_) + h * 64 + d0;
            #pragma unroll
            for (int u = 0; u < 4; ++u) {
                float4 k4 = *(const float4*)(ksrc + u * 4);
                Ks[d0 + u*4 + 0][row] = k4.x; Ks[d0 + u*4 + 1][row] = k4.y;
                Ks[d0 + u*4 + 2][row] = k4.z; Ks[d0 + u*4 + 3][row] = k4.w;
                *(float4*)&Vs[row][d0 + u * 4] = *(const float4*)(vsrc + u * 4);
            }
        }
        __syncthreads();

        // S = Q^T K  (4x4 micro tile per thread)
        float s[4][4];
        #pragma unroll
        for (int i = 0; i < 4; ++i)
            #pragma unroll
            for (int j = 0; j < 4; ++j) s[i][j] = 0.0f;
        #pragma unroll
        for (int d = 0; d < 64; ++d) {
            float4 a4 = *(const float4*)&Qs[d][ty * 4];
            float4 b4 = *(const float4*)&Ks[d][tx * 4];
            float a[4] = {a4.x, a4.y, a4.z, a4.w};
            float b[4] = {b4.x, b4.y, b4.z, b4.w};
            #pragma unroll
            for (int i = 0; i < 4; ++i)
                #pragma unroll
                for (int j = 0; j < 4; ++j)
                    s[i][j] = fmaf(a[i], b[j], s[i][j]);
        }
        // scale + alibi + causal mask
        #pragma unroll
        for (int i = 0; i < 4; ++i) {
            int ig = q0 + ty * 4 + i;
            #pragma unroll
            for (int j = 0; j < 4; ++j) {
                int jg = n0 + tx * 4 + j;
                float val = s[i][j] * 0.125f + slope * (float)(ig - jg);
                s[i][j] = (jg <= ig) ? val : -1e30f;
            }
        }
        // online softmax per row (16 threads per row, within half-warp)
        #pragma unroll
        for (int i = 0; i < 4; ++i) {
            float lm = fmaxf(fmaxf(s[i][0], s[i][1]), fmaxf(s[i][2], s[i][3]));
            #pragma unroll
            for (int off = 8; off >= 1; off >>= 1)
                lm = fmaxf(lm, __shfl_xor_sync(0xffffffffu, lm, off));
            float m_new = fmaxf(m_prev[i], lm);
            float scale = expf(m_prev[i] - m_new);
            float rs = 0.0f;
            #pragma unroll
            for (int j = 0; j < 4; ++j) {
                float p = expf(s[i][j] - m_new);
                s[i][j] = p;
                rs += p;
            }
            #pragma unroll
            for (int off = 8; off >= 1; off >>= 1)
                rs += __shfl_xor_sync(0xffffffffu, rs, off);
            l_prev[i] = l_prev[i] * scale + rs;
            m_prev[i] = m_new;
            #pragma unroll
            for (int j = 0; j < 4; ++j) o[i][j] *= scale;
            #pragma unroll
            for (int j = 0; j < 4; ++j) Ps[ty * 4 + i][tx * 4 + j] = s[i][j];
        }
        __syncthreads();
        // O += P @ V
        #pragma unroll
        for (int n = 0; n < 64; ++n) {
            float a[4];
            #pragma unroll
            for (int i = 0; i < 4; ++i) a[i] = Ps[ty * 4 + i][n];
            float4 b4 = *(const float4*)&Vs[n][tx * 4];
            float b[4] = {b4.x, b4.y, b4.z, b4.w};
            #pragma unroll
            for (int i = 0; i < 4; ++i)
                #pragma unroll
                for (int j = 0; j < 4; ++j)
                    o[i][j] = fmaf(a[i], b[j], o[i][j]);
        }
        __syncthreads();
    }

    #pragma unroll
    for (int i = 0; i < 4; ++i) {
        float inv = 1.0f / l_prev[i];
        float* dst = O + ((size_t)(b * T_ + q0 + ty * 4 + i) * E_) + h * 64 + tx * 4;
        #pragma unroll
        for (int j = 0; j < 4; ++j) dst[j] = o[i][j] * inv;
    }
}

// -------- hierarchy pooling --------
// K1[b,c,e] = mean_{t=(32+c)*16 .. +16} Kf[b,t,e], c in 0..63
__global__ void pool1_kernel(const float* __restrict__ Kf, const float* __restrict__ Vf,
                             float* __restrict__ K1, float* __restrict__ V1) {
    int idx = blockIdx.x * blockDim.x + threadIdx.x;
    if (idx >= B_ * 64 * E_) return;
    int e = idx & (E_ - 1);
    int c = (idx >> 10) & 63;
    int b = idx >> 16;
    int t0 = (32 + c) * 16;
    float sk = 0.0f, sv = 0.0f;
    #pragma unroll
    for (int u = 0; u < 16; ++u) {
        size_t off = ((size_t)(b * T_ + t0 + u) * E_) + e;
        sk += Kf[off]; sv += Vf[off];
    }
    K1[idx] = sk * (1.0f / 16.0f);
    V1[idx] = sv * (1.0f / 16.0f);
}

__global__ void pool2_kernel(const float* __restrict__ K1, const float* __restrict__ V1,
                             float* __restrict__ K2, float* __restrict__ V2) {
    int idx = blockIdx.x * blockDim.x + threadIdx.x;
    if (idx >= B_ * 32 * E_) return;
    int e = idx & (E_ - 1);
    int p = (idx >> 10) & 31;
    int b = idx >> 15;
    size_t base = ((size_t)(b * 64 + 2 * p) * E_) + e;
    K2[idx] = 0.5f * (K1[base] + K1[base + E_]);
    V2[idx] = 0.5f * (V1[base] + V1[base + E_]);
}

// -------- hierarchical attention: ctx = attend(K1,V1) + attend(K2,V2) -----
// grid (T/64, B*H), 64 threads; one thread per query.
__global__ void __launch_bounds__(64)
hier_attn_kernel(const float* __restrict__ Qh,
                 const float* __restrict__ K1, const float* __restrict__ V1,
                 const float* __restrict__ K2, const float* __restrict__ V2,
                 float* __restrict__ ctx) {
    __shared__ float Qs[64][64];   // [d][t]
    __shared__ float Ks[64][64];   // [m][d]
    __shared__ float Vs[64][64];   // [m][d]

    const int bh = blockIdx.y;
    const int b = bh / H_;
    const int h = bh % H_;
    const int t0 = blockIdx.x * 64;
    const int tid = threadIdx.x;

    // load my Q row transposed
    {
        const float* qsrc = Qh + ((size_t)(b * T_ + t0 + tid) * E_) + h * 64;
        #pragma unroll
        for (int d = 0; d < 64; d += 4) {
            float4 v4 = *(const float4*)(qsrc + d);
            Qs[d + 0][tid] = v4.x; Qs[d + 1][tid] = v4.y;
            Qs[d + 2][tid] = v4.z; Qs[d + 3][tid] = v4.w;
        }
    }

    float out[64];
    #pragma unroll
    for (int d = 0; d < 64; ++d) out[d] = 0.0f;

    #pragma unroll 1
    for (int phase = 0; phase < 2; ++phase) {
        const float* Kp = phase ? K2 : K1;
        const float* Vp = phase ? V2 : V1;
        const int Tm = phase ? 32 : 64;
        const int Trows = phase ? 32 : 64;
        __syncthreads();
        for (int i = tid; i < Tm * 16; i += 64) {
            int r = i >> 4;
            int c = (i & 15) * 4;
            size_t off = ((size_t)(b * Trows + r) * E_) + h * 64 + c;
            *(float4*)&Ks[r][c] = *(const float4*)(Kp + off);
            *(float4*)&Vs[r][c] = *(const float4*)(Vp + off);
        }
        __syncthreads();

        // pass 1: row max
        float mx = -1e30f;
        for (int m = 0; m < Tm; ++m) {
            float s = 0.0f;
            #pragma unroll
            for (int d = 0; d < 64; ++d) s = fmaf(Qs[d][tid], Ks[m][d], s);
            mx = fmaxf(mx, s * 0.125f);
        }
        // pass 2: exp + accumulate
        float sum = 0.0f;
        float outp[64];
        #pragma unroll
        for (int d = 0; d < 64; ++d) outp[d] = 0.0f;
        for (int m = 0; m < Tm; ++m) {
            float s = 0.0f;
            #pragma unroll
            for (int d = 0; d < 64; ++d) s = fmaf(Qs[d][tid], Ks[m][d], s);
            float p = expf(s * 0.125f - mx);
            sum += p;
            #pragma unroll
            for (int d = 0; d < 64; ++d) outp[d] = fmaf(p, Vs[m][d], outp[d]);
        }
        float inv = 1.0f / sum;
        #pragma unroll
        for (int d = 0; d < 64; ++d) out[d] += outp[d] * inv;
    }

    float* dst = ctx + ((size_t)(b * T_ + t0 + tid) * E_) + h * 64;
    #pragma unroll
    for (int d = 0; d < 64; d += 4) {
        float4 v4 = make_float4(out[d], out[d + 1], out[d + 2], out[d + 3]);
        *(float4*)(dst + d) = v4;
    }
}

__global__ void zero_tail_kernel(float* p, int n) {
    int i = blockIdx.x * blockDim.x + threadIdx.x;
    if (i < n) p[i] = 0.0f;
}

// -------- launch --------
extern "C" void kernel_launch(void* const* d_in, const int* in_sizes, int n_in,
                              void* d_out, int out_size) {
    const float* x      = (const float*)d_in[0];
    const float* Wq_w   = (const float*)d_in[1];
    const float* Wq_A   = (const float*)d_in[2];
    const float* Wq_B   = (const float*)d_in[3];
    const float* Wk_w   = (const float*)d_in[4];
    const float* Wk_A   = (const float*)d_in[5];
    const float* Wk_B   = (const float*)d_in[6];
    const float* Wv_w   = (const float*)d_in[7];
    const float* Wv_A   = (const float*)d_in[8];
    const float* Wv_B   = (const float*)d_in[9];
    const float* proj_w = (const float*)d_in[10];
    const float* hq_w   = (const float*)d_in[11];
    const float* hp_w   = (const float*)d_in[12];
    const float* gate   = (const float*)d_in[13];
    const float* slopes = (const float*)d_in[14];
    float* out = (float*)d_out;

    float *wq, *wk, *wv, *q, *k, *v, *qh, *attn, *ctx, *K1, *V1, *K2, *V2;
    cudaGetSymbolAddress((void**)&wq, g_Wq);
    cudaGetSymbolAddress((void**)&wk, g_Wk);
    cudaGetSymbolAddress((void**)&wv, g_Wv);
    cudaGetSymbolAddress((void**)&q, g_q);
    cudaGetSymbolAddress((void**)&k, g_k);
    cudaGetSymbolAddress((void**)&v, g_v);
    cudaGetSymbolAddress((void**)&qh, g_qh);
    cudaGetSymbolAddress((void**)&attn, g_attn);
    cudaGetSymbolAddress((void**)&ctx, g_ctx);
    cudaGetSymbolAddress((void**)&K1, g_K1);
    cudaGetSymbolAddress((void**)&V1, g_V1);
    cudaGetSymbolAddress((void**)&K2, g_K2);
    cudaGetSymbolAddress((void**)&V2, g_V2);

    // 1. fold LoRA into effective weights
    fold_lora_kernel<<<(E_ * E_) / 256, 256>>>(Wq_w, Wq_A, Wq_B, wq);
    fold_lora_kernel<<<(E_ * E_) / 256, 256>>>(Wk_w, Wk_A, Wk_B, wk);
    fold_lora_kernel<<<(E_ * E_) / 256, 256>>>(Wv_w, Wv_A, Wv_B, wv);

    // 2. projections
    dim3 gg(E_ / 128, BT_ / 128);
    sgemm_nt_kernel<<<gg, 256>>>(x, wq, q, BT_, E_, E_, nullptr, 0);
    sgemm_nt_kernel<<<gg, 256>>>(x, wk, k, BT_, E_, E_, nullptr, 0);
    sgemm_nt_kernel<<<gg, 256>>>(x, wv, v, BT_, E_, E_, nullptr, 0);
    sgemm_nt_kernel<<<gg, 256>>>(x, hq_w, qh, BT_, E_, E_, nullptr, 0);

    // 3. causal attention with alibi
    flash_attn_kernel<<<dim3(T_ / 64, B_ * H_), 256>>>(q, k, v, slopes, attn);

    // 4. hierarchy pooling + small attention
    pool1_kernel<<<(B_ * 64 * E_) / 256, 256>>>(k, v, K1, V1);
    pool2_kernel<<<(B_ * 32 * E_) / 256, 256>>>(K1, V1, K2, V2);
    hier_attn_kernel<<<dim3(T_ / 64, B_ * H_), 64>>>(qh, K1, V1, K2, V2, ctx);

    // 5. output projections: out = attn@proj.T + sigmoid(gate)*(ctx@hp.T)
    sgemm_nt_kernel<<<gg, 256>>>(attn, proj_w, out, BT_, E_, E_, nullptr, 0);
    sgemm_nt_kernel<<<gg, 256>>>(ctx, hp_w, out, BT_, E_, E_, gate, 1);

    // 6. recon output is exactly zero
    if (out_size > BTE_) {
        int tail = out_size - BTE_;
        zero_tail_kernel<<<(tail + 255) / 256, 256>>>(out + BTE_, tail);
    }
}

// round 2
// speedup vs baseline: 1.8429x; 1.8429x over previous
#include <cuda_runtime.h>
#include <math.h>
#include <stdint.h>

#define B_  4
#define T_  2048
#define E_  1024
#define H_  16
#define DH_ 64
#define BT_ (B_*T_)
#define BTE_ (B_*T_*E_)

// -------- scratch (device globals; no allocation allowed) --------
__device__ float g_Wq[E_*E_];
__device__ float g_Wk[E_*E_];
__device__ float g_Wv[E_*E_];
__device__ float g_q[BTE_];
__device__ float g_k[BTE_];
__device__ float g_v[BTE_];
__device__ float g_qh[BTE_];
__device__ float g_attn[BTE_];
__device__ float g_ctx[BTE_];
__device__ float g_K1[B_*64*E_];
__device__ float g_V1[B_*64*E_];
__device__ float g_K2[B_*32*E_];
__device__ float g_V2[B_*32*E_];

// -------- fold LoRA: Weff = W + 2 * A @ Bm  (A: E x 8, Bm: 8 x E) --------
__global__ void fold_lora_kernel(const float* __restrict__ W,
                                 const float* __restrict__ A,
                                 const float* __restrict__ Bm,
                                 float* __restrict__ Weff) {
    int idx = blockIdx.x * blockDim.x + threadIdx.x;   // over E*E
    int n = idx >> 10;          // row (output feature)
    int k = idx & 1023;         // col (input feature)
    float acc = W[idx];
    #pragma unroll
    for (int r = 0; r < 8; ++r)
        acc += 2.0f * A[n * 8 + r] * Bm[r * E_ + k];
    Weff[idx] = acc;
}

// ======================= tf32 tensor-core GEMM (NT) =======================
// C[m,n] = (acc? C : 0) + alpha * sum_k A[m,k]*B[n,k]
// A: M x K row-major, B: N x K row-major.
// Tile 128x128x32, 256 threads (8 warps, 2x4), warp tile 64x32 (4x4 m16n8k8).

__device__ __forceinline__ float to_tf32(float x) {
    uint32_t u;
    asm("cvt.rna.tf32.f32 %0, %1;" : "=r"(u) : "f"(x));
    return __uint_as_float(u);
}

__device__ __forceinline__ void mma_tf32(float* c,
                                         uint32_t a0, uint32_t a1, uint32_t a2, uint32_t a3,
                                         uint32_t b0, uint32_t b1) {
    asm volatile(
        "mma.sync.aligned.m16n8k8.row.col.f32.tf32.tf32.f32 "
        "{%0,%1,%2,%3},{%4,%5,%6,%7},{%8,%9},{%0,%1,%2,%3};"
        : "+f"(c[0]), "+f"(c[1]), "+f"(c[2]), "+f"(c[3])
        : "r"(a0), "r"(a1), "r"(a2), "r"(a3), "r"(b0), "r"(b1));
}

#define GBM 128
#define GBN 128
#define GBK 32
#define GPAD 4
#define GSTRIDE (GBK + GPAD)   // 36 floats per row

__global__ void __launch_bounds__(256)
gemm_tf32_nt_kernel(const float* __restrict__ A, const float* __restrict__ Bmat,
                    float* __restrict__ C, int M, int N, int K,
                    const float* __restrict__ gate, int accumulate) {
    __shared__ float As[GBM][GSTRIDE];
    __shared__ float Bs[GBN][GSTRIDE];

    const int tid  = threadIdx.x;
    const int warp = tid >> 5;
    const int lane = tid & 31;
    const int wm = warp >> 2;        // 0..1
    const int wn = warp & 3;         // 0..3
    const int groupID = lane >> 2;   // 0..7
    const int tig = lane & 3;        // 0..3

    const int bm = blockIdx.y * GBM;
    const int bn = blockIdx.x * GBN;

    float c[4][4][4];
    #pragma unroll
    for (int i = 0; i < 4; ++i)
        #pragma unroll
        for (int j = 0; j < 4; ++j)
            #pragma unroll
            for (int r = 0; r < 4; ++r) c[i][j][r] = 0.0f;

    // global staging: 4 float4 per thread per matrix per stage
    float4 ra[4], rb[4];
    int lm[4], lkq[4];
    #pragma unroll
    for (int u = 0; u < 4; ++u) {
        int lin = tid + u * 256;         // 0..1023 (float4 units)
        lm[u]  = lin >> 3;               // 0..127
        lkq[u] = (lin & 7) << 2;         // 0,4,...,28
    }

    // prologue: load stage 0
    #pragma unroll
    for (int u = 0; u < 4; ++u) {
        ra[u] = *(const float4*)(A    + (size_t)(bm + lm[u]) * K + lkq[u]);
        rb[u] = *(const float4*)(Bmat + (size_t)(bn + lm[u]) * K + lkq[u]);
    }
    #pragma unroll
    for (int u = 0; u < 4; ++u) {
        float* pa = &As[lm[u]][lkq[u]];
        float* pb = &Bs[lm[u]][lkq[u]];
        pa[0] = to_tf32(ra[u].x); pa[1] = to_tf32(ra[u].y);
        pa[2] = to_tf32(ra[u].z); pa[3] = to_tf32(ra[u].w);
        pb[0] = to_tf32(rb[u].x); pb[1] = to_tf32(rb[u].y);
        pb[2] = to_tf32(rb[u].z); pb[3] = to_tf32(rb[u].w);
    }
    __syncthreads();

    for (int k0 = GBK; k0 <= K; k0 += GBK) {
        // prefetch next stage into registers
        if (k0 < K) {
            #pragma unroll
            for (int u = 0; u < 4; ++u) {
                ra[u] = *(const float4*)(A    + (size_t)(bm + lm[u]) * K + k0 + lkq[u]);
                rb[u] = *(const float4*)(Bmat + (size_t)(bn + lm[u]) * K + k0 + lkq[u]);
            }
        }

        // compute current stage
        #pragma unroll
        for (int ks = 0; ks < GBK; ks += 8) {
            uint32_t af[4][4], bf[4][2];
            #pragma unroll
            for (int mt = 0; mt < 4; ++mt) {
                int m = wm * 64 + mt * 16;
                af[mt][0] = __float_as_uint(As[m + groupID    ][ks + tig    ]);
                af[mt][1] = __float_as_uint(As[m + groupID + 8][ks + tig    ]);
                af[mt][2] = __float_as_uint(As[m + groupID    ][ks + tig + 4]);
                af[mt][3] = __float_as_uint(As[m + groupID + 8][ks + tig + 4]);
            }
            #pragma unroll
            for (int nt = 0; nt < 4; ++nt) {
                int n = wn * 32 + nt * 8;
                bf[nt][0] = __float_as_uint(Bs[n + groupID][ks + tig    ]);
                bf[nt][1] = __float_as_uint(Bs[n + groupID][ks + tig + 4]);
            }
            #pragma unroll
            for (int mt = 0; mt < 4; ++mt)
                #pragma unroll
                for (int nt = 0; nt < 4; ++nt)
                    mma_tf32(c[mt][nt], af[mt][0], af[mt][1], af[mt][2], af[mt][3],
                             bf[nt][0], bf[nt][1]);
        }
        __syncthreads();

        if (k0 < K) {
            #pragma unroll
            for (int u = 0; u < 4; ++u) {
                float* pa = &As[lm[u]][lkq[u]];
                float* pb = &Bs[lm[u]][lkq[u]];
                pa[0] = to_tf32(ra[u].x); pa[1] = to_tf32(ra[u].y);
                pa[2] = to_tf32(ra[u].z); pa[3] = to_tf32(ra[u].w);
                pb[0] = to_tf32(rb[u].x); pb[1] = to_tf32(rb[u].y);
                pb[2] = to_tf32(rb[u].z); pb[3] = to_tf32(rb[u].w);
            }
            __syncthreads();
        }
    }

    float alpha = 1.0f;
    if (gate) alpha = 1.0f / (1.0f + expf(-__ldg(gate)));   // sigmoid(gate)

    #pragma unroll
    for (int mt = 0; mt < 4; ++mt) {
        #pragma unroll
        for (int nt = 0; nt < 4; ++nt) {
            int row0 = bm + wm * 64 + mt * 16 + groupID;
            int col  = bn + wn * 32 + nt * 8 + tig * 2;
            float* p0 = C + (size_t)row0 * N + col;
            float* p1 = C + (size_t)(row0 + 8) * N + col;
            if (accumulate) {
                p0[0] += alpha * c[mt][nt][0];
                p0[1] += alpha * c[mt][nt][1];
                p1[0] += alpha * c[mt][nt][2];
                p1[1] += alpha * c[mt][nt][3];
            } else {
                p0[0] = alpha * c[mt][nt][0];
                p0[1] = alpha * c[mt][nt][1];
                p1[0] = alpha * c[mt][nt][2];
                p1[1] = alpha * c[mt][nt][3];
            }
        }
    }
}

// -------- flash attention, causal + alibi(+slope*(i-j)), fp32 -------------
// grid: (T/64, B*H), 256 threads. Tiles 64(q) x 64(k) x 64(d).
__global__ void __launch_bounds__(256)
flash_attn_kernel(const float* __restrict__ Q, const float* __restrict__ K,
                  const float* __restrict__ V, const float* __restrict__ slopes,
                  float* __restrict__ O) {
    __shared__ float Qs[64][64];   // [d][m]
    __shared__ float Ks[64][64];   // [d][n]
    __shared__ float Vs[64][64];   // [n][d]
    __shared__ float Ps[64][65];   // [m][n] padded

    const int bh = blockIdx.y;
    const int b = bh / H_;
    const int h = bh % H_;
    const int q0 = blockIdx.x * 64;
    const int tid = threadIdx.x;
    const int tx = tid & 15;
    const int ty = tid >> 4;

    // load Q tile transposed: Qs[d][m]
    {
        int row = tid >> 2;
        int d0 = (tid & 3) * 16;
        const float* src = Q + ((size_t)(b * T_ + q0 + row) * E_) + h * 64 + d0;
        #pragma unroll
        for (int u = 0; u < 4; ++u) {
            float4 v4 = *(const float4*)(src + u * 4);
            Qs[d0 + u*4 + 0][row] = v4.x; Qs[d0 + u*4 + 1][row] = v4.y;
            Qs[d0 + u*4 + 2][row] = v4.z; Qs[d0 + u*4 + 3][row] = v4.w;
        }
    }
    const float slope = slopes[h];

    float o[4][4];
    float m_prev[4], l_prev[4];
    #pragma unroll
    for (int i = 0; i < 4; ++i) {
        m_prev[i] = -1e30f; l_prev[i] = 0.0f;
        #pragma unroll
        for (int j = 0; j < 4; ++j) o[i][j] = 0.0f;
    }

    const int ntiles = blockIdx.x + 1;   // causal
    for (int jt = 0; jt < ntiles; ++jt) {
        const int n0 = jt * 64;
        {
            int row = tid >> 2;
            int d0 = (tid & 3) * 16;
            const float* ksrc = K + ((size_t)(b * T_ + n0 + row) * E_) + h * 64 + d0;
            const float* vsrc = V + ((size_t)(b * T_ + n0 + row) * E_) + h * 64 + d0;
            #pragma unroll
            for (int u = 0; u < 4; ++u) {
                float4 k4 = *(const float4*)(ksrc + u * 4);
                Ks[d0 + u*4 + 0][row] = k4.x; Ks[d0 + u*4 + 1][row] = k4.y;
                Ks[d0 + u*4 + 2][row] = k4.z; Ks[d0 + u*4 + 3][row] = k4.w;
                *(float4*)&Vs[row][d0 + u * 4] = *(const float4*)(vsrc + u * 4);
            }
        }
        __syncthreads();

        float s[4][4];
        #pragma unroll
        for (int i = 0; i < 4; ++i)
            #pragma unroll
            for (int j = 0; j < 4; ++j) s[i][j] = 0.0f;
        #pragma unroll
        for (int d = 0; d < 64; ++d) {
            float4 a4 = *(const float4*)&Qs[d][ty * 4];
            float4 b4 = *(const float4*)&Ks[d][tx * 4];
            float a[4] = {a4.x, a4.y, a4.z, a4.w};
            float b[4] = {b4.x, b4.y, b4.z, b4.w};
            #pragma unroll
            for (int i = 0; i < 4; ++i)
                #pragma unroll
                for (int j = 0; j < 4; ++j)
                    s[i][j] = fmaf(a[i], b[j], s[i][j]);
        }
        #pragma unroll
        for (int i = 0; i < 4; ++i) {
            int ig = q0 + ty * 4 + i;
            #pragma unroll
            for (int j = 0; j < 4; ++j) {
                int jg = n0 + tx * 4 + j;
                float val = s[i][j] * 0.125f + slope * (float)(ig - jg);
                s[i][j] = (jg <= ig) ? val : -1e30f;
            }
        }
        #pragma unroll
        for (int i = 0; i < 4; ++i) {
            float lm = fmaxf(fmaxf(s[i][0], s[i][1]), fmaxf(s[i][2], s[i][3]));
            #pragma unroll
            for (int off = 8; off >= 1; off >>= 1)
                lm = fmaxf(lm, __shfl_xor_sync(0xffffffffu, lm, off));
            float m_new = fmaxf(m_prev[i], lm);
            float scale = expf(m_prev[i] - m_new);
            float rs = 0.0f;
            #pragma unroll
            for (int j = 0; j < 4; ++j) {
                float p = expf(s[i][j] - m_new);
                s[i][j] = p;
                rs += p;
            }
            #pragma unroll
            for (int off = 8; off >= 1; off >>= 1)
                rs += __shfl_xor_sync(0xffffffffu, rs, off);
            l_prev[i] = l_prev[i] * scale + rs;
            m_prev[i] = m_new;
            #pragma unroll
            for (int j = 0; j < 4; ++j) o[i][j] *= scale;
            #pragma unroll
            for (int j = 0; j < 4; ++j) Ps[ty * 4 + i][tx * 4 + j] = s[i][j];
        }
        __syncthreads();
        #pragma unroll
        for (int n = 0; n < 64; ++n) {
            float a[4];
            #pragma unroll
            for (int i = 0; i < 4; ++i) a[i] = Ps[ty * 4 + i][n];
            float4 b4 = *(const float4*)&Vs[n][tx * 4];
            float b[4] = {b4.x, b4.y, b4.z, b4.w};
            #pragma unroll
            for (int i = 0; i < 4; ++i)
                #pragma unroll
                for (int j = 0; j < 4; ++j)
                    o[i][j] = fmaf(a[i], b[j], o[i][j]);
        }
        __syncthreads();
    }

    #pragma unroll
    for (int i = 0; i < 4; ++i) {
        float inv = 1.0f / l_prev[i];
        float* dst = O + ((size_t)(b * T_ + q0 + ty * 4 + i) * E_) + h * 64 + tx * 4;
        #pragma unroll
        for (int j = 0; j < 4; ++j) dst[j] = o[i][j] * inv;
    }
}

// -------- hierarchy pooling --------
__global__ void pool1_kernel(const float* __restrict__ Kf, const float* __restrict__ Vf,
                             float* __restrict__ K1, float* __restrict__ V1) {
    int idx = blockIdx.x * blockDim.x + threadIdx.x;
    if (idx >= B_ * 64 * E_) return;
    int e = idx & (E_ - 1);
    int c = (idx >> 10) & 63;
    int b = idx >> 16;
    int t0 = (32 + c) * 16;
    float sk = 0.0f, sv = 0.0f;
    #pragma unroll
    for (int u = 0; u < 16; ++u) {
        size_t off = ((size_t)(b * T_ + t0 + u) * E_) + e;
        sk += Kf[off]; sv += Vf[off];
    }
    K1[idx] = sk * (1.0f / 16.0f);
    V1[idx] = sv * (1.0f / 16.0f);
}

__global__ void pool2_kernel(const float* __restrict__ K1, const float* __restrict__ V1,
                             float* __restrict__ K2, float* __restrict__ V2) {
    int idx = blockIdx.x * blockDim.x + threadIdx.x;
    if (idx >= B_ * 32 * E_) return;
    int e = idx & (E_ - 1);
    int p = (idx >> 10) & 31;
    int b = idx >> 15;
    size_t base = ((size_t)(b * 64 + 2 * p) * E_) + e;
    K2[idx] = 0.5f * (K1[base] + K1[base + E_]);
    V2[idx] = 0.5f * (V1[base] + V1[base + E_]);
}

// -------- hierarchical attention: ctx = attend(K1,V1) + attend(K2,V2) -----
__global__ void __launch_bounds__(64)
hier_attn_kernel(const float* __restrict__ Qh,
                 const float* __restrict__ K1, const float* __restrict__ V1,
                 const float* __restrict__ K2, const float* __restrict__ V2,
                 float* __restrict__ ctx) {
    __shared__ float Qs[64][64];   // [d][t]
    __shared__ float Ks[64][64];   // [m][d]
    __shared__ float Vs[64][64];   // [m][d]

    const int bh = blockIdx.y;
    const int b = bh / H_;
    const int h = bh % H_;
    const int t0 = blockIdx.x * 64;
    const int tid = threadIdx.x;

    {
        const float* qsrc = Qh + ((size_t)(b * T_ + t0 + tid) * E_) + h * 64;
        #pragma unroll
        for (int d = 0; d < 64; d += 4) {
            float4 v4 = *(const float4*)(qsrc + d);
            Qs[d + 0][tid] = v4.x; Qs[d + 1][tid] = v4.y;
            Qs[d + 2][tid] = v4.z; Qs[d + 3][tid] = v4.w;
        }
    }

    float out[64];
    #pragma unroll
    for (int d = 0; d < 64; ++d) out[d] = 0.0f;

    #pragma unroll 1
    for (int phase = 0; phase < 2; ++phase) {
        const float* Kp = phase ? K2 : K1;
        const float* Vp = phase ? V2 : V1;
        const int Tm = phase ? 32 : 64;
        const int Trows = phase ? 32 : 64;
        __syncthreads();
        for (int i = tid; i < Tm * 16; i += 64) {
            int r = i >> 4;
            int c = (i & 15) * 4;
            size_t off = ((size_t)(b * Trows + r) * E_) + h * 64 + c;
            *(float4*)&Ks[r][c] = *(const float4*)(Kp + off);
            *(float4*)&Vs[r][c] = *(const float4*)(Vp + off);
        }
        __syncthreads();

        float mx = -1e30f;
        for (int m = 0; m < Tm; ++m) {
            float s = 0.0f;
            #pragma unroll
            for (int d = 0; d < 64; ++d) s = fmaf(Qs[d][tid], Ks[m][d], s);
            mx = fmaxf(mx, s * 0.125f);
        }
        float sum = 0.0f;
        float outp[64];
        #pragma unroll
        for (int d = 0; d < 64; ++d) outp[d] = 0.0f;
        for (int m = 0; m < Tm; ++m) {
            float s = 0.0f;
            #pragma unroll
            for (int d = 0; d < 64; ++d) s = fmaf(Qs[d][tid], Ks[m][d], s);
            float p = expf(s * 0.125f - mx);
            sum += p;
            #pragma unroll
            for (int d = 0; d < 64; ++d) outp[d] = fmaf(p, Vs[m][d], outp[d]);
        }
        float inv = 1.0f / sum;
        #pragma unroll
        for (int d = 0; d < 64; ++d) out[d] += outp[d] * inv;
    }

    float* dst = ctx + ((size_t)(b * T_ + t0 + tid) * E_) + h * 64;
    #pragma unroll
    for (int d = 0; d < 64; d += 4) {
        float4 v4 = make_float4(out[d], out[d + 1], out[d + 2], out[d + 3]);
        *(float4*)(dst + d) = v4;
    }
}

__global__ void zero_tail_kernel(float* p, int n) {
    int i = blockIdx.x * blockDim.x + threadIdx.x;
    if (i < n) p[i] = 0.0f;
}

// -------- launch --------
extern "C" void kernel_launch(void* const* d_in, const int* in_sizes, int n_in,
                              void* d_out, int out_size) {
    const float* x      = (const float*)d_in[0];
    const float* Wq_w   = (const float*)d_in[1];
    const float* Wq_A   = (const float*)d_in[2];
    const float* Wq_B   = (const float*)d_in[3];
    const float* Wk_w   = (const float*)d_in[4];
    const float* Wk_A   = (const float*)d_in[5];
    const float* Wk_B   = (const float*)d_in[6];
    const float* Wv_w   = (const float*)d_in[7];
    const float* Wv_A   = (const float*)d_in[8];
    const float* Wv_B   = (const float*)d_in[9];
    const float* proj_w = (const float*)d_in[10];
    const float* hq_w   = (const float*)d_in[11];
    const float* hp_w   = (const float*)d_in[12];
    const float* gate   = (const float*)d_in[13];
    const float* slopes = (const float*)d_in[14];
    float* out = (float*)d_out;

    float *wq, *wk, *wv, *q, *k, *v, *qh, *attn, *ctx, *K1, *V1, *K2, *V2;
    cudaGetSymbolAddress((void**)&wq, g_Wq);
    cudaGetSymbolAddress((void**)&wk, g_Wk);
    cudaGetSymbolAddress((void**)&wv, g_Wv);
    cudaGetSymbolAddress((void**)&q, g_q);
    cudaGetSymbolAddress((void**)&k, g_k);
    cudaGetSymbolAddress((void**)&v, g_v);
    cudaGetSymbolAddress((void**)&qh, g_qh);
    cudaGetSymbolAddress((void**)&attn, g_attn);
    cudaGetSymbolAddress((void**)&ctx, g_ctx);
    cudaGetSymbolAddress((void**)&K1, g_K1);
    cudaGetSymbolAddress((void**)&V1, g_V1);
    cudaGetSymbolAddress((void**)&K2, g_K2);
    cudaGetSymbolAddress((void**)&V2, g_V2);

    // 1. fold LoRA into effective weights
    fold_lora_kernel<<<(E_ * E_) / 256, 256>>>(Wq_w, Wq_A, Wq_B, wq);
    fold_lora_kernel<<<(E_ * E_) / 256, 256>>>(Wk_w, Wk_A, Wk_B, wk);
    fold_lora_kernel<<<(E_ * E_) / 256, 256>>>(Wv_w, Wv_A, Wv_B, wv);

    // 2. projections (tf32 tensor cores)
    dim3 gg(E_ / GBN, BT_ / GBM);
    gemm_tf32_nt_kernel<<<gg, 256>>>(x, wq, q, BT_, E_, E_, nullptr, 0);
    gemm_tf32_nt_kernel<<<gg, 256>>>(x, wk, k, BT_, E_, E_, nullptr, 0);
    gemm_tf32_nt_kernel<<<gg, 256>>>(x, wv, v, BT_, E_, E_, nullptr, 0);
    gemm_tf32_nt_kernel<<<gg, 256>>>(x, hq_w, qh, BT_, E_, E_, nullptr, 0);

    // 3. causal attention with alibi
    flash_attn_kernel<<<dim3(T_ / 64, B_ * H_), 256>>>(q, k, v, slopes, attn);

    // 4. hierarchy pooling + small attention
    pool1_kernel<<<(B_ * 64 * E_) / 256, 256>>>(k, v, K1, V1);
    pool2_kernel<<<(B_ * 32 * E_) / 256, 256>>>(K1, V1, K2, V2);
    hier_attn_kernel<<<dim3(T_ / 64, B_ * H_), 64>>>(qh, K1, V1, K2, V2, ctx);

    // 5. output projections: out = attn@proj.T + sigmoid(gate)*(ctx@hp.T)
    gemm_tf32_nt_kernel<<<gg, 256>>>(attn, proj_w, out, BT_, E_, E_, nullptr, 0);
    gemm_tf32_nt_kernel<<<gg, 256>>>(ctx, hp_w, out, BT_, E_, E_, gate, 1);

    // 6. recon output is exactly zero
    if (out_size > BTE_) {
        int tail = out_size - BTE_;
        zero_tail_kernel<<<(tail + 255) / 256, 256>>>(out + BTE_, tail);
    }
}

// round 3
// speedup vs baseline: 2.4377x; 1.3228x over previous
#include <cuda_runtime.h>
#include <math.h>
#include <stdint.h>

#define B_  4
#define T_  2048
#define E_  1024
#define H_  16
#define DH_ 64
#define BT_ (B_*T_)
#define BTE_ (B_*T_*E_)

// -------- scratch (device globals; no allocation allowed) --------
__device__ float g_Wq[E_*E_];
__device__ float g_Wk[E_*E_];
__device__ float g_Wv[E_*E_];
__device__ float g_q[BTE_];
__device__ float g_k[BTE_];
__device__ float g_v[BTE_];
__device__ float g_qh[BTE_];
__device__ float g_attn[BTE_];
__device__ float g_ctx[BTE_];
__device__ float g_K1[B_*64*E_];
__device__ float g_V1[B_*64*E_];
__device__ float g_K2[B_*32*E_];
__device__ float g_V2[B_*32*E_];

// -------- helpers --------
__device__ __forceinline__ uint32_t tf32u(float x) {
    uint32_t u;
    asm("cvt.rna.tf32.f32 %0, %1;" : "=r"(u) : "f"(x));
    return u;
}
__device__ __forceinline__ float tf32f(float x) { return __uint_as_float(tf32u(x)); }

__device__ __forceinline__ void mma_tf32(float* c,
                                         uint32_t a0, uint32_t a1, uint32_t a2, uint32_t a3,
                                         uint32_t b0, uint32_t b1) {
    asm volatile(
        "mma.sync.aligned.m16n8k8.row.col.f32.tf32.tf32.f32 "
        "{%0,%1,%2,%3},{%4,%5,%6,%7},{%8,%9},{%0,%1,%2,%3};"
        : "+f"(c[0]), "+f"(c[1]), "+f"(c[2]), "+f"(c[3])
        : "r"(a0), "r"(a1), "r"(a2), "r"(a3), "r"(b0), "r"(b1));
}

// -------- fold LoRA: Weff = W + 2 * A @ Bm  (A: E x 8, Bm: 8 x E) --------
__global__ void fold_lora_kernel(const float* __restrict__ W,
                                 const float* __restrict__ A,
                                 const float* __restrict__ Bm,
                                 float* __restrict__ Weff) {
    int idx = blockIdx.x * blockDim.x + threadIdx.x;   // over E*E
    int n = idx >> 10;
    int k = idx & 1023;
    float acc = W[idx];
    #pragma unroll
    for (int r = 0; r < 8; ++r)
        acc += 2.0f * A[n * 8 + r] * Bm[r * E_ + k];
    Weff[idx] = acc;
}

// ======================= tf32 tensor-core GEMM (NT) =======================
#define GBM 128
#define GBN 128
#define GBK 32
#define GPAD 4
#define GSTRIDE (GBK + GPAD)

__global__ void __launch_bounds__(256)
gemm_tf32_nt_kernel(const float* __restrict__ A, const float* __restrict__ Bmat,
                    float* __restrict__ C, int M, int N, int K,
                    const float* __restrict__ gate, int accumulate) {
    __shared__ float As[GBM][GSTRIDE];
    __shared__ float Bs[GBN][GSTRIDE];

    const int tid  = threadIdx.x;
    const int warp = tid >> 5;
    const int lane = tid & 31;
    const int wm = warp >> 2;
    const int wn = warp & 3;
    const int groupID = lane >> 2;
    const int tig = lane & 3;

    const int bm = blockIdx.y * GBM;
    const int bn = blockIdx.x * GBN;

    float c[4][4][4];
    #pragma unroll
    for (int i = 0; i < 4; ++i)
        #pragma unroll
        for (int j = 0; j < 4; ++j)
            #pragma unroll
            for (int r = 0; r < 4; ++r) c[i][j][r] = 0.0f;

    float4 ra[4], rb[4];
    int lm[4], lkq[4];
    #pragma unroll
    for (int u = 0; u < 4; ++u) {
        int lin = tid + u * 256;
        lm[u]  = lin >> 3;
        lkq[u] = (lin & 7) << 2;
    }

    #pragma unroll
    for (int u = 0; u < 4; ++u) {
        ra[u] = *(const float4*)(A    + (size_t)(bm + lm[u]) * K + lkq[u]);
        rb[u] = *(const float4*)(Bmat + (size_t)(bn + lm[u]) * K + lkq[u]);
    }
    #pragma unroll
    for (int u = 0; u < 4; ++u) {
        float* pa = &As[lm[u]][lkq[u]];
        float* pb = &Bs[lm[u]][lkq[u]];
        pa[0] = tf32f(ra[u].x); pa[1] = tf32f(ra[u].y);
        pa[2] = tf32f(ra[u].z); pa[3] = tf32f(ra[u].w);
        pb[0] = tf32f(rb[u].x); pb[1] = tf32f(rb[u].y);
        pb[2] = tf32f(rb[u].z); pb[3] = tf32f(rb[u].w);
    }
    __syncthreads();

    for (int k0 = GBK; k0 <= K; k0 += GBK) {
        if (k0 < K) {
            #pragma unroll
            for (int u = 0; u < 4; ++u) {
                ra[u] = *(const float4*)(A    + (size_t)(bm + lm[u]) * K + k0 + lkq[u]);
                rb[u] = *(const float4*)(Bmat + (size_t)(bn + lm[u]) * K + k0 + lkq[u]);
            }
        }

        #pragma unroll
        for (int ks = 0; ks < GBK; ks += 8) {
            uint32_t af[4][4], bf[4][2];
            #pragma unroll
            for (int mt = 0; mt < 4; ++mt) {
                int m = wm * 64 + mt * 16;
                af[mt][0] = __float_as_uint(As[m + groupID    ][ks + tig    ]);
                af[mt][1] = __float_as_uint(As[m + groupID + 8][ks + tig    ]);
                af[mt][2] = __float_as_uint(As[m + groupID    ][ks + tig + 4]);
                af[mt][3] = __float_as_uint(As[m + groupID + 8][ks + tig + 4]);
            }
            #pragma unroll
            for (int nt = 0; nt < 4; ++nt) {
                int n = wn * 32 + nt * 8;
                bf[nt][0] = __float_as_uint(Bs[n + groupID][ks + tig    ]);
                bf[nt][1] = __float_as_uint(Bs[n + groupID][ks + tig + 4]);
            }
            #pragma unroll
            for (int mt = 0; mt < 4; ++mt)
                #pragma unroll
                for (int nt = 0; nt < 4; ++nt)
                    mma_tf32(c[mt][nt], af[mt][0], af[mt][1], af[mt][2], af[mt][3],
                             bf[nt][0], bf[nt][1]);
        }
        __syncthreads();

        if (k0 < K) {
            #pragma unroll
            for (int u = 0; u < 4; ++u) {
                float* pa = &As[lm[u]][lkq[u]];
                float* pb = &Bs[lm[u]][lkq[u]];
                pa[0] = tf32f(ra[u].x); pa[1] = tf32f(ra[u].y);
                pa[2] = tf32f(ra[u].z); pa[3] = tf32f(ra[u].w);
                pb[0] = tf32f(rb[u].x); pb[1] = tf32f(rb[u].y);
                pb[2] = tf32f(rb[u].z); pb[3] = tf32f(rb[u].w);
            }
            __syncthreads();
        }
    }

    float alpha = 1.0f;
    if (gate) alpha = 1.0f / (1.0f + expf(-__ldg(gate)));

    #pragma unroll
    for (int mt = 0; mt < 4; ++mt) {
        #pragma unroll
        for (int nt = 0; nt < 4; ++nt) {
            int row0 = bm + wm * 64 + mt * 16 + groupID;
            int col  = bn + wn * 32 + nt * 8 + tig * 2;
            float* p0 = C + (size_t)row0 * N + col;
            float* p1 = C + (size_t)(row0 + 8) * N + col;
            if (accumulate) {
                p0[0] += alpha * c[mt][nt][0];
                p0[1] += alpha * c[mt][nt][1];
                p1[0] += alpha * c[mt][nt][2];
                p1[1] += alpha * c[mt][nt][3];
            } else {
                p0[0] = alpha * c[mt][nt][0];
                p0[1] = alpha * c[mt][nt][1];
                p1[0] = alpha * c[mt][nt][2];
                p1[1] = alpha * c[mt][nt][3];
            }
        }
    }
}

// ============ flash attention with tf32 tensor cores ============
// grid (T/64, B*H), 128 threads (4 warps). Each warp: 16 q-rows x 64 k-cols.
// KP buffer: stages Q, then holds K tile, then reused for P. Vs holds V tile.
__global__ void __launch_bounds__(128)
flash_tf32_kernel(const float* __restrict__ Q, const float* __restrict__ K,
                  const float* __restrict__ V, const float* __restrict__ slopes,
                  float* __restrict__ O) {
    __shared__ float KP[64][68];
    __shared__ float Vs[64][72];

    const int bh = blockIdx.y;
    const int b = bh >> 4;
    const int h = bh & 15;
    const int q0 = blockIdx.x * 64;
    const int tid = threadIdx.x;
    const int warp = tid >> 5;
    const int lane = tid & 31;
    const int g = lane >> 2;       // groupID 0..7
    const int tg = lane & 3;       // 0..3
    const float slope = slopes[h];

    const int ldrow = tid >> 1;
    const int ldcol = (tid & 1) * 32;

    // stage Q into KP, pick up fragments into registers
    {
        const float* src = Q + ((size_t)(b * T_ + q0 + ldrow)) * E_ + h * 64 + ldcol;
        #pragma unroll
        for (int u = 0; u < 8; ++u)
            *(float4*)&KP[ldrow][ldcol + u * 4] = *(const float4*)(src + u * 4);
    }
    __syncthreads();
    uint32_t qf[8][4];
    #pragma unroll
    for (int c = 0; c < 8; ++c) {
        qf[c][0] = tf32u(KP[warp * 16 + g    ][c * 8 + tg    ]);
        qf[c][1] = tf32u(KP[warp * 16 + g + 8][c * 8 + tg    ]);
        qf[c][2] = tf32u(KP[warp * 16 + g    ][c * 8 + tg + 4]);
        qf[c][3] = tf32u(KP[warp * 16 + g + 8][c * 8 + tg + 4]);
    }
    __syncthreads();

    float o[8][4];
    #pragma unroll
    for (int dt = 0; dt < 8; ++dt)
        #pragma unroll
        for (int r = 0; r < 4; ++r) o[dt][r] = 0.0f;

    float m0 = -1e30f, m1 = -1e30f, l0 = 0.0f, l1 = 0.0f;
    const int r0 = q0 + warp * 16 + g;
    const int r1 = r0 + 8;

    const int lastjt = blockIdx.x;
    for (int jt = 0; jt <= lastjt; ++jt) {
        const int n0 = jt * 64;
        // load K, V tiles (tf32-converted at store)
        {
            const float* ksrc = K + ((size_t)(b * T_ + n0 + ldrow)) * E_ + h * 64 + ldcol;
            const float* vsrc = V + ((size_t)(b * T_ + n0 + ldrow)) * E_ + h * 64 + ldcol;
            #pragma unroll
            for (int u = 0; u < 8; ++u) {
                float4 kk = *(const float4*)(ksrc + u * 4);
                float4 vv = *(const float4*)(vsrc + u * 4);
                *(float4*)&KP[ldrow][ldcol + u * 4] =
                    make_float4(tf32f(kk.x), tf32f(kk.y), tf32f(kk.z), tf32f(kk.w));
                *(float4*)&Vs[ldrow][ldcol + u * 4] =
                    make_float4(tf32f(vv.x), tf32f(vv.y), tf32f(vv.z), tf32f(vv.w));
            }
        }
        __syncthreads();

        // S = Q @ K^T
        float sa[8][4];
        #pragma unroll
        for (int nt = 0; nt < 8; ++nt)
            #pragma unroll
            for (int r = 0; r < 4; ++r) sa[nt][r] = 0.0f;
        #pragma unroll
        for (int c = 0; c < 8; ++c) {
            #pragma unroll
            for (int nt = 0; nt < 8; ++nt) {
                uint32_t b0 = __float_as_uint(KP[nt * 8 + g][c * 8 + tg    ]);
                uint32_t b1 = __float_as_uint(KP[nt * 8 + g][c * 8 + tg + 4]);
                mma_tf32(sa[nt], qf[c][0], qf[c][1], qf[c][2], qf[c][3], b0, b1);
            }
        }
        __syncthreads();   // all warps done reading K before P overwrites KP

        // scale + alibi + mask, row maxes
        float mx0 = -1e30f, mx1 = -1e30f;
        const bool diag = (jt == lastjt);
        #pragma unroll
        for (int nt = 0; nt < 8; ++nt) {
            int kc0 = n0 + nt * 8 + tg * 2;
            float a00 = slope * (float)(r0 - kc0);
            float a01 = a00 - slope;
            float a10 = slope * (float)(r1 - kc0);
            float a11 = a10 - slope;
            float v00 = fmaf(sa[nt][0], 0.125f, a00);
            float v01 = fmaf(sa[nt][1], 0.125f, a01);
            float v10 = fmaf(sa[nt][2], 0.125f, a10);
            float v11 = fmaf(sa[nt][3], 0.125f, a11);
            if (diag) {
                if (kc0     > r0) v00 = -1e30f;
                if (kc0 + 1 > r0) v01 = -1e30f;
                if (kc0     > r1) v10 = -1e30f;
                if (kc0 + 1 > r1) v11 = -1e30f;
            }
            sa[nt][0] = v00; sa[nt][1] = v01; sa[nt][2] = v10; sa[nt][3] = v11;
            mx0 = fmaxf(mx0, fmaxf(v00, v01));
            mx1 = fmaxf(mx1, fmaxf(v10, v11));
        }
        mx0 = fmaxf(mx0, __shfl_xor_sync(0xffffffffu, mx0, 1));
        mx0 = fmaxf(mx0, __shfl_xor_sync(0xffffffffu, mx0, 2));
        mx1 = fmaxf(mx1, __shfl_xor_sync(0xffffffffu, mx1, 1));
        mx1 = fmaxf(mx1, __shfl_xor_sync(0xffffffffu, mx1, 2));

        float mn0 = fmaxf(m0, mx0);
        float mn1 = fmaxf(m1, mx1);
        float sc0 = __expf(m0 - mn0);
        float sc1 = __expf(m1 - mn1);
        float rs0 = 0.0f, rs1 = 0.0f;
        #pragma unroll
        for (int nt = 0; nt < 8; ++nt) {
            float p00 = tf32f(__expf(sa[nt][0] - mn0));
            float p01 = tf32f(__expf(sa[nt][1] - mn0));
            float p10 = tf32f(__expf(sa[nt][2] - mn1));
            float p11 = tf32f(__expf(sa[nt][3] - mn1));
            rs0 += p00 + p01;
            rs1 += p10 + p11;
            *(float2*)&KP[warp * 16 + g    ][nt * 8 + tg * 2] = make_float2(p00, p01);
            *(float2*)&KP[warp * 16 + g + 8][nt * 8 + tg * 2] = make_float2(p10, p11);
        }
        rs0 += __shfl_xor_sync(0xffffffffu, rs0, 1);
        rs0 += __shfl_xor_sync(0xffffffffu, rs0, 2);
        rs1 += __shfl_xor_sync(0xffffffffu, rs1, 1);
        rs1 += __shfl_xor_sync(0xffffffffu, rs1, 2);

        l0 = l0 * sc0 + rs0;
        l1 = l1 * sc1 + rs1;
        m0 = mn0; m1 = mn1;
        #pragma unroll
        for (int dt = 0; dt < 8; ++dt) {
            o[dt][0] *= sc0; o[dt][1] *= sc0;
            o[dt][2] *= sc1; o[dt][3] *= sc1;
        }
        __syncwarp();

        // O += P @ V   (P read from own warp band of KP)
        #pragma unroll
        for (int kc = 0; kc < 8; ++kc) {
            uint32_t a0 = __float_as_uint(KP[warp * 16 + g    ][kc * 8 + tg    ]);
            uint32_t a1 = __float_as_uint(KP[warp * 16 + g + 8][kc * 8 + tg    ]);
            uint32_t a2 = __float_as_uint(KP[warp * 16 + g    ][kc * 8 + tg + 4]);
            uint32_t a3 = __float_as_uint(KP[warp * 16 + g + 8][kc * 8 + tg + 4]);
            #pragma unroll
            for (int dt = 0; dt < 8; ++dt) {
                uint32_t b0 = __float_as_uint(Vs[kc * 8 + tg    ][dt * 8 + g]);
                uint32_t b1 = __float_as_uint(Vs[kc * 8 + tg + 4][dt * 8 + g]);
                mma_tf32(o[dt], a0, a1, a2, a3, b0, b1);
            }
        }
        __syncthreads();   // before next tile's K/V store
    }

    float il0 = 1.0f / l0, il1 = 1.0f / l1;
    #pragma unroll
    for (int dt = 0; dt < 8; ++dt) {
        float* d0 = O + ((size_t)(b * T_ + r0)) * E_ + h * 64 + dt * 8 + tg * 2;
        float* d1 = O + ((size_t)(b * T_ + r1)) * E_ + h * 64 + dt * 8 + tg * 2;
        *(float2*)d0 = make_float2(o[dt][0] * il0, o[dt][1] * il0);
        *(float2*)d1 = make_float2(o[dt][2] * il1, o[dt][3] * il1);
    }
}

// -------- hierarchy pooling --------
__global__ void pool1_kernel(const float* __restrict__ Kf, const float* __restrict__ Vf,
                             float* __restrict__ K1, float* __restrict__ V1) {
    int idx = blockIdx.x * blockDim.x + threadIdx.x;
    if (idx >= B_ * 64 * E_) return;
    int e = idx & (E_ - 1);
    int c = (idx >> 10) & 63;
    int b = idx >> 16;
    int t0 = (32 + c) * 16;
    float sk = 0.0f, sv = 0.0f;
    #pragma unroll
    for (int u = 0; u < 16; ++u) {
        size_t off = ((size_t)(b * T_ + t0 + u) * E_) + e;
        sk += Kf[off]; sv += Vf[off];
    }
    K1[idx] = sk * (1.0f / 16.0f);
    V1[idx] = sv * (1.0f / 16.0f);
}

__global__ void pool2_kernel(const float* __restrict__ K1, const float* __restrict__ V1,
                             float* __restrict__ K2, float* __restrict__ V2) {
    int idx = blockIdx.x * blockDim.x + threadIdx.x;
    if (idx >= B_ * 32 * E_) return;
    int e = idx & (E_ - 1);
    int p = (idx >> 10) & 31;
    int b = idx >> 15;
    size_t base = ((size_t)(b * 64 + 2 * p) * E_) + e;
    K2[idx] = 0.5f * (K1[base] + K1[base + E_]);
    V2[idx] = 0.5f * (V1[base] + V1[base + E_]);
}

// -------- hierarchical attention --------
__global__ void __launch_bounds__(64)
hier_attn_kernel(const float* __restrict__ Qh,
                 const float* __restrict__ K1, const float* __restrict__ V1,
                 const float* __restrict__ K2, const float* __restrict__ V2,
                 float* __restrict__ ctx) {
    __shared__ float Qs[64][64];
    __shared__ float Ks[64][64];
    __shared__ float Vs[64][64];

    const int bh = blockIdx.y;
    const int b = bh / H_;
    const int h = bh % H_;
    const int t0 = blockIdx.x * 64;
    const int tid = threadIdx.x;

    {
        const float* qsrc = Qh + ((size_t)(b * T_ + t0 + tid) * E_) + h * 64;
        #pragma unroll
        for (int d = 0; d < 64; d += 4) {
            float4 v4 = *(const float4*)(qsrc + d);
            Qs[d + 0][tid] = v4.x; Qs[d + 1][tid] = v4.y;
            Qs[d + 2][tid] = v4.z; Qs[d + 3][tid] = v4.w;
        }
    }

    float out[64];
    #pragma unroll
    for (int d = 0; d < 64; ++d) out[d] = 0.0f;

    #pragma unroll 1
    for (int phase = 0; phase < 2; ++phase) {
        const float* Kp = phase ? K2 : K1;
        const float* Vp = phase ? V2 : V1;
        const int Tm = phase ? 32 : 64;
        const int Trows = phase ? 32 : 64;
        __syncthreads();
        for (int i = tid; i < Tm * 16; i += 64) {
            int r = i >> 4;
            int c = (i & 15) * 4;
            size_t off = ((size_t)(b * Trows + r) * E_) + h * 64 + c;
            *(float4*)&Ks[r][c] = *(const float4*)(Kp + off);
            *(float4*)&Vs[r][c] = *(const float4*)(Vp + off);
        }
        __syncthreads();

        float mx = -1e30f;
        for (int m = 0; m < Tm; ++m) {
            float s = 0.0f;
            #pragma unroll
            for (int d = 0; d < 64; ++d) s = fmaf(Qs[d][tid], Ks[m][d], s);
            mx = fmaxf(mx, s * 0.125f);
        }
        float sum = 0.0f;
        float outp[64];
        #pragma unroll
        for (int d = 0; d < 64; ++d) outp[d] = 0.0f;
        for (int m = 0; m < Tm; ++m) {
            float s = 0.0f;
            #pragma unroll
            for (int d = 0; d < 64; ++d) s = fmaf(Qs[d][tid], Ks[m][d], s);
            float p = expf(s * 0.125f - mx);
            sum += p;
            #pragma unroll
            for (int d = 0; d < 64; ++d) outp[d] = fmaf(p, Vs[m][d], outp[d]);
        }
        float inv = 1.0f / sum;
        #pragma unroll
        for (int d = 0; d < 64; ++d) out[d] += outp[d] * inv;
    }

    float* dst = ctx + ((size_t)(b * T_ + t0 + tid) * E_) + h * 64;
    #pragma unroll
    for (int d = 0; d < 64; d += 4) {
        float4 v4 = make_float4(out[d], out[d + 1], out[d + 2], out[d + 3]);
        *(float4*)(dst + d) = v4;
    }
}

__global__ void zero_tail_kernel(float* p, int n) {
    int i = blockIdx.x * blockDim.x + threadIdx.x;
    if (i < n) p[i] = 0.0f;
}

// -------- launch --------
extern "C" void kernel_launch(void* const* d_in, const int* in_sizes, int n_in,
                              void* d_out, int out_size) {
    const float* x      = (const float*)d_in[0];
    const float* Wq_w   = (const float*)d_in[1];
    const float* Wq_A   = (const float*)d_in[2];
    const float* Wq_B   = (const float*)d_in[3];
    const float* Wk_w   = (const float*)d_in[4];
    const float* Wk_A   = (const float*)d_in[5];
    const float* Wk_B   = (const float*)d_in[6];
    const float* Wv_w   = (const float*)d_in[7];
    const float* Wv_A   = (const float*)d_in[8];
    const float* Wv_B   = (const float*)d_in[9];
    const float* proj_w = (const float*)d_in[10];
    const float* hq_w   = (const float*)d_in[11];
    const float* hp_w   = (const float*)d_in[12];
    const float* gate   = (const float*)d_in[13];
    const float* slopes = (const float*)d_in[14];
    float* out = (float*)d_out;

    float *wq, *wk, *wv, *q, *k, *v, *qh, *attn, *ctx, *K1, *V1, *K2, *V2;
    cudaGetSymbolAddress((void**)&wq, g_Wq);
    cudaGetSymbolAddress((void**)&wk, g_Wk);
    cudaGetSymbolAddress((void**)&wv, g_Wv);
    cudaGetSymbolAddress((void**)&q, g_q);
    cudaGetSymbolAddress((void**)&k, g_k);
    cudaGetSymbolAddress((void**)&v, g_v);
    cudaGetSymbolAddress((void**)&qh, g_qh);
    cudaGetSymbolAddress((void**)&attn, g_attn);
    cudaGetSymbolAddress((void**)&ctx, g_ctx);
    cudaGetSymbolAddress((void**)&K1, g_K1);
    cudaGetSymbolAddress((void**)&V1, g_V1);
    cudaGetSymbolAddress((void**)&K2, g_K2);
    cudaGetSymbolAddress((void**)&V2, g_V2);

    // 1. fold LoRA into effective weights
    fold_lora_kernel<<<(E_ * E_) / 256, 256>>>(Wq_w, Wq_A, Wq_B, wq);
    fold_lora_kernel<<<(E_ * E_) / 256, 256>>>(Wk_w, Wk_A, Wk_B, wk);
    fold_lora_kernel<<<(E_ * E_) / 256, 256>>>(Wv_w, Wv_A, Wv_B, wv);

    // 2. projections (tf32 tensor cores)
    dim3 gg(E_ / GBN, BT_ / GBM);
    gemm_tf32_nt_kernel<<<gg, 256>>>(x, wq, q, BT_, E_, E_, nullptr, 0);
    gemm_tf32_nt_kernel<<<gg, 256>>>(x, wk, k, BT_, E_, E_, nullptr, 0);
    gemm_tf32_nt_kernel<<<gg, 256>>>(x, wv, v, BT_, E_, E_, nullptr, 0);
    gemm_tf32_nt_kernel<<<gg, 256>>>(x, hq_w, qh, BT_, E_, E_, nullptr, 0);

    // 3. causal attention with alibi (tf32 tensor cores)
    flash_tf32_kernel<<<dim3(T_ / 64, B_ * H_), 128>>>(q, k, v, slopes, attn);

    // 4. hierarchy pooling + small attention
    pool1_kernel<<<(B_ * 64 * E_) / 256, 256>>>(k, v, K1, V1);
    pool2_kernel<<<(B_ * 32 * E_) / 256, 256>>>(K1, V1, K2, V2);
    hier_attn_kernel<<<dim3(T_ / 64, B_ * H_), 64>>>(qh, K1, V1, K2, V2, ctx);

    // 5. output projections
    gemm_tf32_nt_kernel<<<gg, 256>>>(attn, proj_w, out, BT_, E_, E_, nullptr, 0);
    gemm_tf32_nt_kernel<<<gg, 256>>>(ctx, hp_w, out, BT_, E_, E_, gate, 1);

    // 6. recon output is exactly zero
    if (out_size > BTE_) {
        int tail = out_size - BTE_;
        zero_tail_kernel<<<(tail + 255) / 256, 256>>>(out + BTE_, tail);
    }
}